// round 4
// baseline (speedup 1.0000x reference)
#include <cuda_runtime.h>
#include <cstdint>

#define NPOS 112            // positions per block; 4032 = 36*112
#define TPB  36
#define NTILES 14           // NPOS/8
#define SMEM_TOTAL (32 * NTILES * 32 * 2 * 4)   // 114688 B fragment-major act buffer

// Fragment-major TF32 weights: chunk[(l*32+kk)*16+mt][lane][4 words], 512B chunks
__device__ __align__(1024) float g_Wt[3 * 65536];

__device__ __forceinline__ float tf32r(float x) {
    uint32_t u; asm("cvt.rna.tf32.f32 %0, %1;" : "=r"(u) : "f"(x));
    return __uint_as_float(u);
}

// float index into fragment-major activation buffer for logical act[r][p]
__device__ __forceinline__ uint32_t faddr(int r, int p) {
    return (uint32_t)(((r >> 3) * NTILES + (p >> 3)) * 64
                      + (p & 7) * 8 + (r & 3) * 2 + ((r >> 2) & 1));
}

__global__ void convert_w_kernel(const float* __restrict__ W1,
                                 const float* __restrict__ W2,
                                 const float* __restrict__ W3) {
    int i = blockIdx.x * blockDim.x + threadIdx.x;   // 196608 threads
    int w = i & 3, lane = (i >> 2) & 31, mt = (i >> 7) & 15, kk = (i >> 11) & 31, l = i >> 16;
    int g = lane >> 2, t = lane & 3;
    int row = mt * 16 + ((w & 1) << 3) + g;
    int col = kk * 8 + ((w >> 1) << 2) + t;
    const float* W = (l == 0) ? W1 : ((l == 1) ? W2 : W3);
    g_Wt[i] = tf32r(W[row * 256 + col]);
}

__device__ __forceinline__ void mma_tf32(float* d, const uint32_t* a,
                                         uint32_t b0, uint32_t b1) {
    asm volatile(
        "mma.sync.aligned.m16n8k8.row.col.f32.tf32.tf32.f32 "
        "{%0,%1,%2,%3}, {%4,%5,%6,%7}, {%8,%9}, {%0,%1,%2,%3};"
        : "+f"(d[0]), "+f"(d[1]), "+f"(d[2]), "+f"(d[3])
        : "r"(a[0]), "r"(a[1]), "r"(a[2]), "r"(a[3]), "r"(b0), "r"(b1));
}

// One block: 256 outputs x 112 positions, 3 fused layers. Warp tile 64 x 56.
__global__ __launch_bounds__(256, 1) void fused_kernel(
    const float* __restrict__ x,      // (32, 64, 64)
    const float* __restrict__ xc,     // (32, 128, 63, 64)
    const float* __restrict__ b1, const float* __restrict__ b2,
    const float* __restrict__ b3,
    float* __restrict__ out)          // (32, 256, 63, 64) with (h,w) flattened to 4032
{
    extern __shared__ float actF[];
    const int tid = threadIdx.x, lane = tid & 31, wid = tid >> 5;
    const int g = lane >> 2, t = lane & 3;
    const int wm = wid >> 1, wn = wid & 1;       // 4 warps in m, 2 in n
    const int b = blockIdx.x / TPB, q0 = (blockIdx.x % TPB) * NPOS;

    // ---- build 256ch x 112pos input tile directly in fragment-major layout ----
    for (int idx = tid; idx < 256 * NPOS; idx += 256) {
        int k = idx / NPOS, j = idx - k * NPOS;
        int q = q0 + j, h = q >> 6, w = q & 63;
        float v;
        if (k < 128)      v = xc[(size_t)(b * 128 + k) * 4032 + q];
        else if (k < 192) v = x[(b * 64 + (k - 128)) * 64 + w];
        else              v = x[(b * 64 + (k - 192)) * 64 + ((w - h - 1) & 63)];
        actF[faddr(k, j)] = tf32r(v);
    }
    __syncthreads();

    const float* biases[3] = {b1, b2, b3};

    for (int l = 0; l < 3; l++) {
        float acc[4][7][4];
        #pragma unroll
        for (int mt = 0; mt < 4; mt++)
            #pragma unroll
            for (int nt = 0; nt < 7; nt++)
                #pragma unroll
                for (int r = 0; r < 4; r++) acc[mt][nt][r] = 0.f;

        const float4* Ab = (const float4*)(g_Wt + ((size_t)l * 32 * 16) * 128) + lane;
        const float2* Bb = (const float2*)actF + lane;

        #pragma unroll 4
        for (int kk = 0; kk < 32; kk++) {
            uint32_t Br[7][2];
            #pragma unroll
            for (int nt = 0; nt < 7; nt++) {
                float2 bv = Bb[(kk * NTILES + wn * 7 + nt) * 32];
                Br[nt][0] = __float_as_uint(bv.x);
                Br[nt][1] = __float_as_uint(bv.y);
            }
            uint32_t Ar[4][4];
            #pragma unroll
            for (int mt = 0; mt < 4; mt++) {
                float4 av = Ab[(kk * 16 + wm * 4 + mt) * 32];
                Ar[mt][0] = __float_as_uint(av.x); Ar[mt][1] = __float_as_uint(av.y);
                Ar[mt][2] = __float_as_uint(av.z); Ar[mt][3] = __float_as_uint(av.w);
            }
            #pragma unroll
            for (int mt = 0; mt < 4; mt++)
                #pragma unroll
                for (int nt = 0; nt < 7; nt++)
                    mma_tf32(acc[mt][nt], Ar[mt], Br[nt][0], Br[nt][1]);
        }

        __syncthreads();   // all warps done reading actF; safe to overwrite in place

        const float* bl = biases[l];
        if (l < 2) {
            #pragma unroll
            for (int mt = 0; mt < 4; mt++) {
                const int R0 = wm * 64 + mt * 16 + g;
                const float bb0 = bl[R0], bb8 = bl[R0 + 8];
                #pragma unroll
                for (int nt = 0; nt < 7; nt++) {
                    const int C0 = wn * 56 + nt * 8 + 2 * t;
                    actF[faddr(R0,     C0)]     = tf32r(fmaxf(acc[mt][nt][0] + bb0, 0.f));
                    actF[faddr(R0,     C0 + 1)] = tf32r(fmaxf(acc[mt][nt][1] + bb0, 0.f));
                    actF[faddr(R0 + 8, C0)]     = tf32r(fmaxf(acc[mt][nt][2] + bb8, 0.f));
                    actF[faddr(R0 + 8, C0 + 1)] = tf32r(fmaxf(acc[mt][nt][3] + bb8, 0.f));
                }
            }
            __syncthreads();
        } else {
            #pragma unroll
            for (int mt = 0; mt < 4; mt++) {
                const int R0 = wm * 64 + mt * 16 + g;
                const float bb0 = bl[R0], bb8 = bl[R0 + 8];
                float* p0 = out + ((size_t)(b * 256 + R0)) * 4032 + q0;
                float* p8 = p0 + (size_t)8 * 4032;
                #pragma unroll
                for (int nt = 0; nt < 7; nt++) {
                    const int C0 = wn * 56 + nt * 8 + 2 * t;
                    p0[C0]     = fmaxf(acc[mt][nt][0] + bb0, 0.f);
                    p0[C0 + 1] = fmaxf(acc[mt][nt][1] + bb0, 0.f);
                    p8[C0]     = fmaxf(acc[mt][nt][2] + bb8, 0.f);
                    p8[C0 + 1] = fmaxf(acc[mt][nt][3] + bb8, 0.f);
                }
            }
        }
    }
}

extern "C" void kernel_launch(void* const* d_in, const int* in_sizes, int n_in,
                              void* d_out, int out_size) {
    const float* x = nullptr; const float* xc = nullptr;
    const float* Ws[3] = {nullptr, nullptr, nullptr};
    const float* Bs[3] = {nullptr, nullptr, nullptr};
    int wi = 0, bi = 0;
    for (int i = 0; i < n_in; i++) {
        int sz = in_sizes[i];
        if (sz == 32 * 64 * 64)              x = (const float*)d_in[i];
        else if (sz == 32 * 128 * 63 * 64)   xc = (const float*)d_in[i];
        else if (sz == 256 * 256 && wi < 3)  Ws[wi++] = (const float*)d_in[i];
        else if (sz == 256 && bi < 3)        Bs[bi++] = (const float*)d_in[i];
    }
    convert_w_kernel<<<768, 256>>>(Ws[0], Ws[1], Ws[2]);
    cudaFuncSetAttribute(fused_kernel,
                         cudaFuncAttributeMaxDynamicSharedMemorySize, SMEM_TOTAL);
    fused_kernel<<<32 * TPB, 256, SMEM_TOTAL>>>(x, xc, Bs[0], Bs[1], Bs[2], (float*)d_out);
}

// round 5
// speedup vs baseline: 2.1099x; 2.1099x over previous
#include <cuda_runtime.h>
#include <cuda_fp16.h>
#include <cstdint>

#define NPOS 112            // positions per block; 4032 = 36*112
#define TPB  36
#define NTILES 14           // NPOS/8
#define SMEM_TOTAL (16 * NTILES * 64 * 4)   // 57344 B: fp16 B-fragment act buffer

// Fragment-major FP16 weights: chunk[(l*16+kt)*16+mt][lane][4 words(b32)] = 512B
__device__ __align__(1024) uint32_t g_Wh[3 * 32768];

// byte offset of logical act[k][p] inside the fp16 B-fragment smem buffer
__device__ __forceinline__ uint32_t faddr16(int k, int p) {
    return (((((uint32_t)(k >> 4) * NTILES + (p >> 3)) * 64
            + ((p & 7) * 4 + ((k >> 1) & 3)) * 2 + ((k >> 3) & 1)) << 2)
            + ((k & 1) << 1));
}

__global__ void convert_w_kernel(const float* __restrict__ W1,
                                 const float* __restrict__ W2,
                                 const float* __restrict__ W3) {
    int i = blockIdx.x * blockDim.x + threadIdx.x;   // 98304 threads, 1 b32 word each
    int reg = i & 3, lane = (i >> 2) & 31, mt = (i >> 7) & 15, kt = (i >> 11) & 15, l = i >> 15;
    int g = lane >> 2, t = lane & 3;
    int row = mt * 16 + g + (reg & 1) * 8;            // output channel o
    int col = kt * 16 + 2 * t + (reg >> 1) * 8;       // input channel c
    const float* W = (l == 0) ? W1 : ((l == 1) ? W2 : W3);
    __half lo = __float2half_rn(W[row * 256 + col]);
    __half hi = __float2half_rn(W[row * 256 + col + 1]);
    g_Wh[i] = (uint32_t)__half_as_ushort(lo) | ((uint32_t)__half_as_ushort(hi) << 16);
}

__device__ __forceinline__ void mma_f16(float* d, const uint32_t* a, const uint32_t* b) {
    asm volatile(
        "mma.sync.aligned.m16n8k16.row.col.f32.f16.f16.f32 "
        "{%0,%1,%2,%3}, {%4,%5,%6,%7}, {%8,%9}, {%0,%1,%2,%3};"
        : "+f"(d[0]), "+f"(d[1]), "+f"(d[2]), "+f"(d[3])
        : "r"(a[0]), "r"(a[1]), "r"(a[2]), "r"(a[3]), "r"(b[0]), "r"(b[1]));
}

// 512 threads = 16 warps (8 m x 2 n); warp tile 32 outputs x 56 positions.
__global__ __launch_bounds__(512, 1) void fused_kernel(
    const float* __restrict__ x,      // (32, 64, 64)
    const float* __restrict__ xc,     // (32, 128, 63, 64)
    const float* __restrict__ b1, const float* __restrict__ b2,
    const float* __restrict__ b3,
    float* __restrict__ out)          // (32, 256, 4032)
{
    extern __shared__ uint32_t actU[];
    char* const sc = (char*)actU;
    const int tid = threadIdx.x, lane = tid & 31, wid = tid >> 5;
    const int g = lane >> 2, t = lane & 3;
    const int wm = wid >> 1, wn = wid & 1;
    const int b = blockIdx.x / TPB, q0 = (blockIdx.x % TPB) * NPOS;

    // build 256ch x 112pos input tile directly as fp16 B-fragments
    for (int idx = tid; idx < 256 * NPOS; idx += 512) {
        int k = idx / NPOS, j = idx - k * NPOS;
        int q = q0 + j, h = q >> 6, w = q & 63;
        float v;
        if (k < 128)      v = xc[(size_t)(b * 128 + k) * 4032 + q];
        else if (k < 192) v = x[(b * 64 + (k - 128)) * 64 + w];
        else              v = x[(b * 64 + (k - 192)) * 64 + ((w - h - 1) & 63)];
        *(__half*)(sc + faddr16(k, j)) = __float2half_rn(v);
    }
    __syncthreads();

    const float* biases[3] = {b1, b2, b3};

    for (int l = 0; l < 3; l++) {
        float acc[2][7][4];
        #pragma unroll
        for (int mt = 0; mt < 2; mt++)
            #pragma unroll
            for (int nt = 0; nt < 7; nt++)
                #pragma unroll
                for (int r = 0; r < 4; r++) acc[mt][nt][r] = 0.f;

        const uint4* Ab = (const uint4*)g_Wh + (size_t)l * 8192 + lane;
        const uint2* Bb = (const uint2*)actU + lane;

        #pragma unroll 2
        for (int kt = 0; kt < 16; kt++) {
            uint32_t Br[7][2];
            #pragma unroll
            for (int nt = 0; nt < 7; nt++) {
                uint2 bv = Bb[(kt * NTILES + wn * 7 + nt) * 32];
                Br[nt][0] = bv.x; Br[nt][1] = bv.y;
            }
            uint32_t Ar[2][4];
            #pragma unroll
            for (int mt = 0; mt < 2; mt++) {
                uint4 av = Ab[(kt * 16 + wm * 2 + mt) * 32];
                Ar[mt][0] = av.x; Ar[mt][1] = av.y; Ar[mt][2] = av.z; Ar[mt][3] = av.w;
            }
            #pragma unroll
            for (int mt = 0; mt < 2; mt++)
                #pragma unroll
                for (int nt = 0; nt < 7; nt++)
                    mma_f16(acc[mt][nt], Ar[mt], Br[nt]);
        }

        __syncthreads();   // everyone done reading actU; safe to overwrite in place

        const float* bl = biases[l];
        if (l < 2) {
            #pragma unroll
            for (int mt = 0; mt < 2; mt++) {
                const int R0 = wm * 32 + mt * 16 + g;
                const float bb0 = bl[R0], bb8 = bl[R0 + 8];
                #pragma unroll
                for (int nt = 0; nt < 7; nt++) {
                    const int C0 = wn * 56 + nt * 8 + 2 * t;
                    *(__half*)(sc + faddr16(R0, C0)) =
                        __float2half_rn(fmaxf(acc[mt][nt][0] + bb0, 0.f));
                    *(__half*)(sc + faddr16(R0, C0 + 1)) =
                        __float2half_rn(fmaxf(acc[mt][nt][1] + bb0, 0.f));
                    *(__half*)(sc + faddr16(R0 + 8, C0)) =
                        __float2half_rn(fmaxf(acc[mt][nt][2] + bb8, 0.f));
                    *(__half*)(sc + faddr16(R0 + 8, C0 + 1)) =
                        __float2half_rn(fmaxf(acc[mt][nt][3] + bb8, 0.f));
                }
            }
            __syncthreads();
        } else {
            #pragma unroll
            for (int mt = 0; mt < 2; mt++) {
                const int R0 = wm * 32 + mt * 16 + g;
                const float bb0 = bl[R0], bb8 = bl[R0 + 8];
                float* p0 = out + ((size_t)(b * 256 + R0)) * 4032 + q0;
                float* p8 = p0 + (size_t)8 * 4032;
                #pragma unroll
                for (int nt = 0; nt < 7; nt++) {
                    const int C0 = wn * 56 + nt * 8 + 2 * t;
                    *(float2*)(p0 + C0) = make_float2(fmaxf(acc[mt][nt][0] + bb0, 0.f),
                                                      fmaxf(acc[mt][nt][1] + bb0, 0.f));
                    *(float2*)(p8 + C0) = make_float2(fmaxf(acc[mt][nt][2] + bb8, 0.f),
                                                      fmaxf(acc[mt][nt][3] + bb8, 0.f));
                }
            }
        }
    }
}

extern "C" void kernel_launch(void* const* d_in, const int* in_sizes, int n_in,
                              void* d_out, int out_size) {
    const float* x = nullptr; const float* xc = nullptr;
    const float* Ws[3] = {nullptr, nullptr, nullptr};
    const float* Bs[3] = {nullptr, nullptr, nullptr};
    int wi = 0, bi = 0;
    for (int i = 0; i < n_in; i++) {
        int sz = in_sizes[i];
        if (sz == 32 * 64 * 64)              x = (const float*)d_in[i];
        else if (sz == 32 * 128 * 63 * 64)   xc = (const float*)d_in[i];
        else if (sz == 256 * 256 && wi < 3)  Ws[wi++] = (const float*)d_in[i];
        else if (sz == 256 && bi < 3)        Bs[bi++] = (const float*)d_in[i];
    }
    convert_w_kernel<<<192, 512>>>(Ws[0], Ws[1], Ws[2]);
    cudaFuncSetAttribute(fused_kernel,
                         cudaFuncAttributeMaxDynamicSharedMemorySize, SMEM_TOTAL);
    fused_kernel<<<32 * TPB, 512, SMEM_TOTAL>>>(x, xc, Bs[0], Bs[1], Bs[2], (float*)d_out);
}